// round 14
// baseline (speedup 1.0000x reference)
#include <cuda_runtime.h>
#include <cuda_bf16.h>
#include <cstdint>

#define N_NODES 50000
#define N_EDGES_MAX 1600000
#define D 128
#define EPS 0.001f
#define CAP 128                  // per-node bucket capacity (P(overflow)~1e-13)

// Scratch (allocation-free rule: __device__ globals)
__device__ float g_h[(size_t)N_NODES * D];
__device__ int   g_degcnt[N_NODES];
__device__ int   g_csrc[(size_t)N_NODES * CAP];   // padded CSR: src ids
__device__ int   g_is64;
// Preconverted weight splits, [n][k] bf16, row stride 136
__device__ __nv_bfloat16 g_wh1[128 * 136];
__device__ __nv_bfloat16 g_wl1[128 * 136];
__device__ __nv_bfloat16 g_wh2[128 * 136];
__device__ __nv_bfloat16 g_wl2[128 * 136];

// ===========================================================================
// Edge-index width detection (JAX x64 ambiguity)
// ===========================================================================
__global__ void detect_kernel(const int* __restrict__ e32) {
    if (threadIdx.x == 0 && blockIdx.x == 0) {
        int is64 = 1;
        #pragma unroll 1
        for (int k = 1; k < 128; k += 2) {
            if (e32[k] != 0) { is64 = 0; break; }
        }
        g_is64 = is64;
    }
}

__global__ void zero_deg_kernel(int* __restrict__ degcnt, int n) {
    int i = blockIdx.x * blockDim.x + threadIdx.x;
    if (i * 4 < n) {
        int4 z = make_int4(0, 0, 0, 0);
        if (i * 4 + 3 < n) *reinterpret_cast<int4*>(degcnt + i * 4) = z;
        else for (int k = i * 4; k < n; k++) degcnt[k] = 0;
    }
}

// ===========================================================================
// Padded-CSR build, 8 edges per thread (deep ILP against ATOMG latency).
// ===========================================================================
__global__ void build_kernel(const void* __restrict__ ei, int E,
                             int* __restrict__ degcnt, int* __restrict__ csrc) {
    int base = (blockIdx.x * blockDim.x + threadIdx.x) * 8;
    if (base >= E) return;
    int ss[8], dd[8];
    int cnt = (E - base < 8) ? (E - base) : 8;
    if (g_is64) {
        if (cnt == 8) {
            const longlong2* eb = reinterpret_cast<const longlong2*>(ei);
            #pragma unroll
            for (int q = 0; q < 4; q++) {
                longlong2 s = __ldg(eb + (base >> 1) + q);
                longlong2 d = __ldg(eb + (size_t)(E >> 1) + (base >> 1) + q);
                ss[2 * q] = (int)s.x; ss[2 * q + 1] = (int)s.y;
                dd[2 * q] = (int)d.x; dd[2 * q + 1] = (int)d.y;
            }
        } else {
            const long long* e = reinterpret_cast<const long long*>(ei);
            for (int k = 0; k < cnt; k++) {
                ss[k] = (int)__ldg(e + base + k);
                dd[k] = (int)__ldg(e + (size_t)E + base + k);
            }
        }
    } else {
        if (cnt == 8) {
            const int4* eb = reinterpret_cast<const int4*>(ei);
            #pragma unroll
            for (int q = 0; q < 2; q++) {
                int4 s = __ldg(eb + (base >> 2) + q);
                int4 d = __ldg(eb + (size_t)(E >> 2) + (base >> 2) + q);
                ss[4 * q] = s.x; ss[4 * q + 1] = s.y; ss[4 * q + 2] = s.z; ss[4 * q + 3] = s.w;
                dd[4 * q] = d.x; dd[4 * q + 1] = d.y; dd[4 * q + 2] = d.z; dd[4 * q + 3] = d.w;
            }
        } else {
            const int* e = reinterpret_cast<const int*>(ei);
            for (int k = 0; k < cnt; k++) {
                ss[k] = __ldg(e + base + k);
                dd[k] = __ldg(e + (size_t)E + base + k);
            }
        }
    }
    int rk[8];
    #pragma unroll
    for (int k = 0; k < 8; k++)
        if (k < cnt) rk[k] = atomicAdd(degcnt + dd[k], 1);
    #pragma unroll
    for (int k = 0; k < 8; k++)
        if (k < cnt && rk[k] < CAP)
            csrc[(size_t)dd[k] * CAP + rk[k]] = ss[k];
}

// ===========================================================================
// Aggregation: one warp per node (byte-identical to R13 pass)
// ===========================================================================
__global__ void agg_kernel(const float* __restrict__ x,
                           const int* __restrict__ csrc,
                           const int* __restrict__ degcnt,
                           float* __restrict__ h, int N) {
    int w = (blockIdx.x * blockDim.x + threadIdx.x) >> 5;
    int lane = threadIdx.x & 31;
    if (w >= N) return;

    float4 acc = *reinterpret_cast<const float4*>(x + (size_t)w * D + lane * 4);
    const float sc = 1.0f + EPS;
    acc.x *= sc; acc.y *= sc; acc.z *= sc; acc.w *= sc;

    const int* lst = csrc + (size_t)w * CAP;
    int deg = degcnt[w];
    if (deg > CAP) deg = CAP;
    int j = 0;
    for (; j + 4 <= deg; j += 4) {
        int a0 = __ldg(lst + j),     a1 = __ldg(lst + j + 1);
        int a2 = __ldg(lst + j + 2), a3 = __ldg(lst + j + 3);
        float4 v0 = *reinterpret_cast<const float4*>(x + (size_t)a0 * D + lane * 4);
        float4 v1 = *reinterpret_cast<const float4*>(x + (size_t)a1 * D + lane * 4);
        float4 v2 = *reinterpret_cast<const float4*>(x + (size_t)a2 * D + lane * 4);
        float4 v3 = *reinterpret_cast<const float4*>(x + (size_t)a3 * D + lane * 4);
        acc.x += (v0.x + v1.x) + (v2.x + v3.x);
        acc.y += (v0.y + v1.y) + (v2.y + v3.y);
        acc.z += (v0.z + v1.z) + (v2.z + v3.z);
        acc.w += (v0.w + v1.w) + (v2.w + v3.w);
    }
    for (; j < deg; j++) {
        int a0 = __ldg(lst + j);
        float4 v0 = *reinterpret_cast<const float4*>(x + (size_t)a0 * D + lane * 4);
        acc.x += v0.x; acc.y += v0.y; acc.z += v0.z; acc.w += v0.w;
    }
    *reinterpret_cast<float4*>(h + (size_t)w * D + lane * 4) = acc;
}

// ===========================================================================
// Weight preconversion: W[k][n] fp32 -> hi/lo bf16 at [n][k], stride 136.
// ===========================================================================
__global__ void wsplit_kernel(const float* __restrict__ W1,
                              const float* __restrict__ W2) {
    const int k = blockIdx.x;
    const int n = threadIdx.x;
    const float* W = blockIdx.y ? W2 : W1;
    __nv_bfloat16* wh = blockIdx.y ? g_wh2 : g_wh1;
    __nv_bfloat16* wl = blockIdx.y ? g_wl2 : g_wl1;
    float v = __ldg(W + (size_t)k * D + n);
    __nv_bfloat16 h = __float2bfloat16(v);
    __nv_bfloat16 l = __float2bfloat16(v - __bfloat162float(h));
    wh[n * 136 + k] = h;
    wl[n * 136 + k] = l;
}

// ===========================================================================
// Tensor-core MLP — mma.sync bf16 3-pass split, 2 CTA/SM,
// DOUBLE-BUFFERED W chunks: copy chunk w+1 overlaps MMA on chunk w.
// ===========================================================================
#define LDA32 68                 // uint32 stride of Ah/Al rows
#define LDB32 9                  // uint32 stride of B chunk rows
#define CHUNK_BYTES (128 * LDB32 * 4)        // 4608 per hi/lo half
#define BUF_BYTES   (2 * CHUNK_BYTES)        // 9216 per buffer (hi+lo)
#define SM_BIAS1 0
#define SM_BIAS2 512
#define SM_AH    1024
#define SM_AL    (SM_AH + 128 * LDA32 * 4)
#define SM_B     (SM_AL + 128 * LDA32 * 4)   // two buffers follow
#define SM_MLP_TOTAL (SM_B + 2 * BUF_BYTES)  // 1024+69632+18432 = 89088

__device__ __forceinline__ void split_pair(float v0, float v1,
                                           uint32_t& hi, uint32_t& lo) {
    __nv_bfloat16 h0 = __float2bfloat16(v0);
    __nv_bfloat16 h1 = __float2bfloat16(v1);
    __nv_bfloat16 l0 = __float2bfloat16(v0 - __bfloat162float(h0));
    __nv_bfloat16 l1 = __float2bfloat16(v1 - __bfloat162float(h1));
    __nv_bfloat162 ph; ph.x = h0; ph.y = h1;
    __nv_bfloat162 pl; pl.x = l0; pl.y = l1;
    hi = *reinterpret_cast<uint32_t*>(&ph);
    lo = *reinterpret_cast<uint32_t*>(&pl);
}

__device__ __forceinline__ void mma_bf16(float* c,
                                         const uint32_t* a,
                                         uint32_t b0, uint32_t b1) {
    asm volatile(
        "mma.sync.aligned.m16n8k16.row.col.f32.bf16.bf16.f32 "
        "{%0,%1,%2,%3}, {%4,%5,%6,%7}, {%8,%9}, {%0,%1,%2,%3};"
        : "+f"(c[0]), "+f"(c[1]), "+f"(c[2]), "+f"(c[3])
        : "r"(a[0]), "r"(a[1]), "r"(a[2]), "r"(a[3]), "r"(b0), "r"(b1));
}

// Copy k-chunk w of the preconverted [n][k] splits into buffer `buf`.
__device__ __forceinline__ void copy_w_chunk(const uint32_t* __restrict__ wh,
                                             const uint32_t* __restrict__ wl,
                                             int w, int buf, char* smem) {
    const int tid = threadIdx.x;
    const int n = tid & 127;
    const uint32_t* src = (tid < 128 ? wh : wl) + n * LDA32 + w * 8;
    uint32_t* dst = reinterpret_cast<uint32_t*>(
        smem + SM_B + buf * BUF_BYTES + (tid < 128 ? 0 : CHUNK_BYTES)) + n * LDB32;
    uint4 v0 = __ldg(reinterpret_cast<const uint4*>(src));
    uint4 v1 = __ldg(reinterpret_cast<const uint4*>(src + 4));
    dst[0] = v0.x; dst[1] = v0.y; dst[2] = v0.z; dst[3] = v0.w;
    dst[4] = v1.x; dst[5] = v1.y; dst[6] = v1.z; dst[7] = v1.w;
}

__global__ void __launch_bounds__(256, 2)
mlp_mma_kernel(const float* __restrict__ H,
               const uint32_t* __restrict__ wh1, const uint32_t* __restrict__ wl1,
               const uint32_t* __restrict__ wh2, const uint32_t* __restrict__ wl2,
               const float* __restrict__ b1, const float* __restrict__ b2,
               float* __restrict__ out, int M) {
    extern __shared__ char smem[];
    uint32_t* ah32 = reinterpret_cast<uint32_t*>(smem + SM_AH);
    uint32_t* al32 = reinterpret_cast<uint32_t*>(smem + SM_AL);
    float* bias1 = reinterpret_cast<float*>(smem + SM_BIAS1);
    float* bias2 = reinterpret_cast<float*>(smem + SM_BIAS2);

    const int tid = threadIdx.x;
    const int wid = tid >> 5;
    const int lane = tid & 31;
    const int g = lane >> 2;
    const int t = lane & 3;
    const int warp_m = wid & 3;
    const int warp_n = wid >> 2;
    const int row_base = blockIdx.x * 128;

    if (tid < 128) bias1[tid] = __ldg(b1 + tid);
    else           bias2[tid - 128] = __ldg(b2 + tid - 128);

    // prefetch W1 chunk 0 into buffer 0
    copy_w_chunk(wh1, wl1, 0, 0, smem);

    // ---- load H tile, split into Ah/Al ----
    {
        const int row = tid >> 1;
        const int c0 = (tid & 1) * 64;
        const bool valid = (row_base + row) < M;
        const float4* src = reinterpret_cast<const float4*>(
            H + (size_t)(row_base + row) * D + c0);
        uint32_t* dh = ah32 + row * LDA32 + (c0 >> 1);
        uint32_t* dl = al32 + row * LDA32 + (c0 >> 1);
        #pragma unroll
        for (int q = 0; q < 16; q++) {
            float4 v = valid ? __ldg(src + q) : make_float4(0.f, 0.f, 0.f, 0.f);
            uint32_t h0, l0, h1, l1;
            split_pair(v.x, v.y, h0, l0);
            split_pair(v.z, v.w, h1, l1);
            dh[q * 2]     = h0;  dh[q * 2 + 1] = h1;
            dl[q * 2]     = l0;  dl[q * 2 + 1] = l1;
        }
    }
    __syncthreads();

    float acc[2][8][4];
    #pragma unroll
    for (int i = 0; i < 2; i++)
        #pragma unroll
        for (int j = 0; j < 8; j++)
            #pragma unroll
            for (int c = 0; c < 4; c++) acc[i][j][c] = 0.f;

    // =============== GEMM1 (double-buffered chunks) ===============
    #pragma unroll 1
    for (int w = 0; w < 8; w++) {
        const int cur = w & 1;
        if (w < 7) copy_w_chunk(wh1, wl1, w + 1, cur ^ 1, smem);

        const uint32_t* bh32 = reinterpret_cast<const uint32_t*>(
            smem + SM_B + cur * BUF_BYTES);
        const uint32_t* bl32 = reinterpret_cast<const uint32_t*>(
            smem + SM_B + cur * BUF_BYTES + CHUNK_BYTES);

        const int kw = w * 8;
        uint32_t ah[2][4], al[2][4];
        #pragma unroll
        for (int mt = 0; mt < 2; mt++) {
            const int r0 = warp_m * 32 + mt * 16 + g;
            const uint32_t* ph = ah32 + r0 * LDA32 + kw + t;
            const uint32_t* pl = al32 + r0 * LDA32 + kw + t;
            ah[mt][0] = ph[0];  ah[mt][2] = ph[4];
            ah[mt][1] = ph[8 * LDA32];  ah[mt][3] = ph[8 * LDA32 + 4];
            al[mt][0] = pl[0];  al[mt][2] = pl[4];
            al[mt][1] = pl[8 * LDA32];  al[mt][3] = pl[8 * LDA32 + 4];
        }
        #pragma unroll
        for (int nt = 0; nt < 8; nt++) {
            const int nr = warp_n * 64 + nt * 8 + g;
            uint32_t bh0 = bh32[nr * LDB32 + t];
            uint32_t bh1 = bh32[nr * LDB32 + t + 4];
            uint32_t bl0 = bl32[nr * LDB32 + t];
            uint32_t bl1 = bl32[nr * LDB32 + t + 4];
            #pragma unroll
            for (int mt = 0; mt < 2; mt++) {
                mma_bf16(acc[mt][nt], ah[mt], bh0, bh1);
                mma_bf16(acc[mt][nt], al[mt], bh0, bh1);
                mma_bf16(acc[mt][nt], ah[mt], bl0, bl1);
            }
        }
        __syncthreads();
    }

    // ---- epilogue 1: bias + relu, re-split into Ah/Al ----
    #pragma unroll
    for (int mt = 0; mt < 2; mt++) {
        const int rl = warp_m * 32 + mt * 16 + g;
        #pragma unroll
        for (int nt = 0; nt < 8; nt++) {
            const int cb = warp_n * 64 + nt * 8 + t * 2;
            float v0 = fmaxf(acc[mt][nt][0] + bias1[cb],     0.f);
            float v1 = fmaxf(acc[mt][nt][1] + bias1[cb + 1], 0.f);
            float v2 = fmaxf(acc[mt][nt][2] + bias1[cb],     0.f);
            float v3 = fmaxf(acc[mt][nt][3] + bias1[cb + 1], 0.f);
            uint32_t hi, lo;
            split_pair(v0, v1, hi, lo);
            ah32[rl * LDA32 + (cb >> 1)] = hi;
            al32[rl * LDA32 + (cb >> 1)] = lo;
            split_pair(v2, v3, hi, lo);
            ah32[(rl + 8) * LDA32 + (cb >> 1)] = hi;
            al32[(rl + 8) * LDA32 + (cb >> 1)] = lo;
            acc[mt][nt][0] = 0.f; acc[mt][nt][1] = 0.f;
            acc[mt][nt][2] = 0.f; acc[mt][nt][3] = 0.f;
        }
    }
    // prefetch W2 chunk 0 into buffer 0 (safe: all GEMM1 buffer reads done
    // before the final mainloop __syncthreads above)
    copy_w_chunk(wh2, wl2, 0, 0, smem);
    __syncthreads();

    // =============== GEMM2 (double-buffered chunks) ===============
    #pragma unroll 1
    for (int w = 0; w < 8; w++) {
        const int cur = w & 1;
        if (w < 7) copy_w_chunk(wh2, wl2, w + 1, cur ^ 1, smem);

        const uint32_t* bh32 = reinterpret_cast<const uint32_t*>(
            smem + SM_B + cur * BUF_BYTES);
        const uint32_t* bl32 = reinterpret_cast<const uint32_t*>(
            smem + SM_B + cur * BUF_BYTES + CHUNK_BYTES);

        const int kw = w * 8;
        uint32_t ah[2][4], al[2][4];
        #pragma unroll
        for (int mt = 0; mt < 2; mt++) {
            const int r0 = warp_m * 32 + mt * 16 + g;
            const uint32_t* ph = ah32 + r0 * LDA32 + kw + t;
            const uint32_t* pl = al32 + r0 * LDA32 + kw + t;
            ah[mt][0] = ph[0];  ah[mt][2] = ph[4];
            ah[mt][1] = ph[8 * LDA32];  ah[mt][3] = ph[8 * LDA32 + 4];
            al[mt][0] = pl[0];  al[mt][2] = pl[4];
            al[mt][1] = pl[8 * LDA32];  al[mt][3] = pl[8 * LDA32 + 4];
        }
        #pragma unroll
        for (int nt = 0; nt < 8; nt++) {
            const int nr = warp_n * 64 + nt * 8 + g;
            uint32_t bh0 = bh32[nr * LDB32 + t];
            uint32_t bh1 = bh32[nr * LDB32 + t + 4];
            uint32_t bl0 = bl32[nr * LDB32 + t];
            uint32_t bl1 = bl32[nr * LDB32 + t + 4];
            #pragma unroll
            for (int mt = 0; mt < 2; mt++) {
                mma_bf16(acc[mt][nt], ah[mt], bh0, bh1);
                mma_bf16(acc[mt][nt], al[mt], bh0, bh1);
                mma_bf16(acc[mt][nt], ah[mt], bl0, bl1);
            }
        }
        __syncthreads();
    }

    // ---- epilogue 2: bias -> out ----
    #pragma unroll
    for (int mt = 0; mt < 2; mt++) {
        const int rl = warp_m * 32 + mt * 16 + g;
        #pragma unroll
        for (int nt = 0; nt < 8; nt++) {
            const int cb = warp_n * 64 + nt * 8 + t * 2;
            if (row_base + rl < M) {
                float2 o;
                o.x = acc[mt][nt][0] + bias2[cb];
                o.y = acc[mt][nt][1] + bias2[cb + 1];
                *reinterpret_cast<float2*>(out + (size_t)(row_base + rl) * D + cb) = o;
            }
            if (row_base + rl + 8 < M) {
                float2 o;
                o.x = acc[mt][nt][2] + bias2[cb];
                o.y = acc[mt][nt][3] + bias2[cb + 1];
                *reinterpret_cast<float2*>(out + (size_t)(row_base + rl + 8) * D + cb) = o;
            }
        }
    }
}

extern "C" void kernel_launch(void* const* d_in, const int* in_sizes, int n_in,
                              void* d_out, int out_size) {
    const float* x  = (const float*)d_in[0];
    const void*  ei = d_in[1];
    const float* W1 = (const float*)d_in[2];
    const float* b1 = (const float*)d_in[3];
    const float* W2 = (const float*)d_in[4];
    const float* b2 = (const float*)d_in[5];
    float* out = (float*)d_out;

    const int N = in_sizes[0] / D;
    const int E = in_sizes[1] / 2;

    float* p_h    = nullptr;
    int*   p_deg  = nullptr;
    int*   p_csrc = nullptr;
    uint32_t *p_wh1 = nullptr, *p_wl1 = nullptr, *p_wh2 = nullptr, *p_wl2 = nullptr;
    cudaGetSymbolAddress((void**)(&p_h),    g_h);
    cudaGetSymbolAddress((void**)(&p_deg),  g_degcnt);
    cudaGetSymbolAddress((void**)(&p_csrc), g_csrc);
    cudaGetSymbolAddress((void**)(&p_wh1),  g_wh1);
    cudaGetSymbolAddress((void**)(&p_wl1),  g_wl1);
    cudaGetSymbolAddress((void**)(&p_wh2),  g_wh2);
    cudaGetSymbolAddress((void**)(&p_wl2),  g_wl2);

    static int attr_set = 0;
    if (!attr_set) {
        cudaFuncSetAttribute(mlp_mma_kernel,
                             cudaFuncAttributeMaxDynamicSharedMemorySize,
                             SM_MLP_TOTAL);
        attr_set = 1;
    }

    detect_kernel<<<1, 32>>>((const int*)ei);
    wsplit_kernel<<<dim3(128, 2), 128>>>(W1, W2);

    zero_deg_kernel<<<(N / 4 + 255) / 256, 256>>>(p_deg, N);
    build_kernel<<<(E / 8 + 255) / 256, 256>>>(ei, E, p_deg, p_csrc);

    agg_kernel<<<(N + 7) / 8, 256>>>(x, p_csrc, p_deg, p_h, N);

    int ntiles = (N + 127) / 128;
    mlp_mma_kernel<<<ntiles, 256, SM_MLP_TOTAL>>>(p_h, p_wh1, p_wl1,
                                                  p_wh2, p_wl2,
                                                  b1, b2, out, N);
}

// round 15
// speedup vs baseline: 1.0255x; 1.0255x over previous
#include <cuda_runtime.h>
#include <cuda_bf16.h>
#include <cstdint>

#define N_NODES 50000
#define N_EDGES_MAX 1600000
#define D 128
#define EPS 0.001f
#define CAP 128                  // per-node bucket capacity (P(overflow)~1e-13)

// Scratch (allocation-free rule: __device__ globals)
__device__ float g_h[(size_t)N_NODES * D];
__device__ int   g_degcnt[N_NODES];
__device__ int   g_csrc[(size_t)N_NODES * CAP];   // padded CSR: src ids
__device__ int   g_is64;
// Preconverted weight splits, [n][k] bf16, row stride 136
__device__ __nv_bfloat16 g_wh1[128 * 136];
__device__ __nv_bfloat16 g_wl1[128 * 136];
__device__ __nv_bfloat16 g_wh2[128 * 136];
__device__ __nv_bfloat16 g_wl2[128 * 136];

// ===========================================================================
// Edge-index width detection (JAX x64 ambiguity)
// ===========================================================================
__global__ void detect_kernel(const int* __restrict__ e32) {
    if (threadIdx.x == 0 && blockIdx.x == 0) {
        int is64 = 1;
        #pragma unroll 1
        for (int k = 1; k < 128; k += 2) {
            if (e32[k] != 0) { is64 = 0; break; }
        }
        g_is64 = is64;
    }
}

__global__ void zero_deg_kernel(int* __restrict__ degcnt, int n) {
    int i = blockIdx.x * blockDim.x + threadIdx.x;
    if (i * 4 < n) {
        int4 z = make_int4(0, 0, 0, 0);
        if (i * 4 + 3 < n) *reinterpret_cast<int4*>(degcnt + i * 4) = z;
        else for (int k = i * 4; k < n; k++) degcnt[k] = 0;
    }
}

// ===========================================================================
// Padded-CSR build (R13 version: 4 edges/thread — measured best; 8/thread
// regressed via occupancy loss, build is at its atomic/sector floor).
// ===========================================================================
__global__ void build_kernel(const void* __restrict__ ei, int E,
                             int* __restrict__ degcnt, int* __restrict__ csrc) {
    int i4 = (blockIdx.x * blockDim.x + threadIdx.x) * 4;
    if (i4 >= E) return;
    int ss[4], dd[4];
    int cnt = (E - i4 < 4) ? (E - i4) : 4;
    if (g_is64) {
        const longlong2* eb = reinterpret_cast<const longlong2*>(ei);
        if (cnt == 4) {
            longlong2 s0 = __ldg(eb + (i4 >> 1));
            longlong2 s1 = __ldg(eb + (i4 >> 1) + 1);
            longlong2 d0 = __ldg(eb + (size_t)(E >> 1) + (i4 >> 1));
            longlong2 d1 = __ldg(eb + (size_t)(E >> 1) + (i4 >> 1) + 1);
            ss[0] = (int)s0.x; ss[1] = (int)s0.y; ss[2] = (int)s1.x; ss[3] = (int)s1.y;
            dd[0] = (int)d0.x; dd[1] = (int)d0.y; dd[2] = (int)d1.x; dd[3] = (int)d1.y;
        } else {
            const long long* e = reinterpret_cast<const long long*>(ei);
            for (int k = 0; k < cnt; k++) {
                ss[k] = (int)__ldg(e + i4 + k);
                dd[k] = (int)__ldg(e + (size_t)E + i4 + k);
            }
        }
    } else {
        const int* e = reinterpret_cast<const int*>(ei);
        if (cnt == 4) {
            int4 s = __ldg(reinterpret_cast<const int4*>(e + i4));
            int4 d = __ldg(reinterpret_cast<const int4*>(e + (size_t)E + i4));
            ss[0] = s.x; ss[1] = s.y; ss[2] = s.z; ss[3] = s.w;
            dd[0] = d.x; dd[1] = d.y; dd[2] = d.z; dd[3] = d.w;
        } else {
            for (int k = 0; k < cnt; k++) {
                ss[k] = __ldg(e + i4 + k);
                dd[k] = __ldg(e + (size_t)E + i4 + k);
            }
        }
    }
    #pragma unroll
    for (int k = 0; k < 4; k++) {
        if (k < cnt) {
            int rank = atomicAdd(degcnt + dd[k], 1);
            if (rank < CAP)
                csrc[(size_t)dd[k] * CAP + rank] = ss[k];
        }
    }
}

// ===========================================================================
// Aggregation: one warp per node; neighbor indices loaded as int4
// (bucket rows are 16B-aligned: CAP=128, j stays a multiple of 4).
// ===========================================================================
__global__ void agg_kernel(const float* __restrict__ x,
                           const int* __restrict__ csrc,
                           const int* __restrict__ degcnt,
                           float* __restrict__ h, int N) {
    int w = (blockIdx.x * blockDim.x + threadIdx.x) >> 5;
    int lane = threadIdx.x & 31;
    if (w >= N) return;

    float4 acc = *reinterpret_cast<const float4*>(x + (size_t)w * D + lane * 4);
    const float sc = 1.0f + EPS;
    acc.x *= sc; acc.y *= sc; acc.z *= sc; acc.w *= sc;

    const int4* lst4 = reinterpret_cast<const int4*>(csrc + (size_t)w * CAP);
    int deg = degcnt[w];
    if (deg > CAP) deg = CAP;
    int j = 0;
    for (; j + 4 <= deg; j += 4) {
        int4 a = __ldg(lst4 + (j >> 2));
        float4 v0 = *reinterpret_cast<const float4*>(x + (size_t)a.x * D + lane * 4);
        float4 v1 = *reinterpret_cast<const float4*>(x + (size_t)a.y * D + lane * 4);
        float4 v2 = *reinterpret_cast<const float4*>(x + (size_t)a.z * D + lane * 4);
        float4 v3 = *reinterpret_cast<const float4*>(x + (size_t)a.w * D + lane * 4);
        acc.x += (v0.x + v1.x) + (v2.x + v3.x);
        acc.y += (v0.y + v1.y) + (v2.y + v3.y);
        acc.z += (v0.z + v1.z) + (v2.z + v3.z);
        acc.w += (v0.w + v1.w) + (v2.w + v3.w);
    }
    const int* lst = csrc + (size_t)w * CAP;
    for (; j < deg; j++) {
        int a0 = __ldg(lst + j);
        float4 v0 = *reinterpret_cast<const float4*>(x + (size_t)a0 * D + lane * 4);
        acc.x += v0.x; acc.y += v0.y; acc.z += v0.z; acc.w += v0.w;
    }
    *reinterpret_cast<float4*>(h + (size_t)w * D + lane * 4) = acc;
}

// ===========================================================================
// Weight preconversion: W[k][n] fp32 -> hi/lo bf16 at [n][k], stride 136.
// ===========================================================================
__global__ void wsplit_kernel(const float* __restrict__ W1,
                              const float* __restrict__ W2) {
    const int k = blockIdx.x;
    const int n = threadIdx.x;
    const float* W = blockIdx.y ? W2 : W1;
    __nv_bfloat16* wh = blockIdx.y ? g_wh2 : g_wh1;
    __nv_bfloat16* wl = blockIdx.y ? g_wl2 : g_wl1;
    float v = __ldg(W + (size_t)k * D + n);
    __nv_bfloat16 h = __float2bfloat16(v);
    __nv_bfloat16 l = __float2bfloat16(v - __bfloat162float(h));
    wh[n * 136 + k] = h;
    wl[n * 136 + k] = l;
}

// ===========================================================================
// Tensor-core MLP — byte-identical to R13 pass (mma.sync bf16 3-pass split,
// 2 CTA/SM, single-buffered W chunks copied coalesced from global splits).
// ===========================================================================
#define LDA32 68
#define LDB32 9
#define SM_BIAS1 0
#define SM_BIAS2 512
#define SM_AH    1024
#define SM_AL    (SM_AH + 128 * LDA32 * 4)
#define SM_BH    (SM_AL + 128 * LDA32 * 4)
#define SM_BL    (SM_BH + 128 * LDB32 * 4)
#define SM_MLP_TOTAL (SM_BL + 128 * LDB32 * 4)      // 79872 bytes

__device__ __forceinline__ void split_pair(float v0, float v1,
                                           uint32_t& hi, uint32_t& lo) {
    __nv_bfloat16 h0 = __float2bfloat16(v0);
    __nv_bfloat16 h1 = __float2bfloat16(v1);
    __nv_bfloat16 l0 = __float2bfloat16(v0 - __bfloat162float(h0));
    __nv_bfloat16 l1 = __float2bfloat16(v1 - __bfloat162float(h1));
    __nv_bfloat162 ph; ph.x = h0; ph.y = h1;
    __nv_bfloat162 pl; pl.x = l0; pl.y = l1;
    hi = *reinterpret_cast<uint32_t*>(&ph);
    lo = *reinterpret_cast<uint32_t*>(&pl);
}

__device__ __forceinline__ void mma_bf16(float* c,
                                         const uint32_t* a,
                                         uint32_t b0, uint32_t b1) {
    asm volatile(
        "mma.sync.aligned.m16n8k16.row.col.f32.bf16.bf16.f32 "
        "{%0,%1,%2,%3}, {%4,%5,%6,%7}, {%8,%9}, {%0,%1,%2,%3};"
        : "+f"(c[0]), "+f"(c[1]), "+f"(c[2]), "+f"(c[3])
        : "r"(a[0]), "r"(a[1]), "r"(a[2]), "r"(a[3]), "r"(b0), "r"(b1));
}

__device__ __forceinline__ void copy_w_chunk(const uint32_t* __restrict__ wh,
                                             const uint32_t* __restrict__ wl,
                                             int w, char* smem) {
    const int tid = threadIdx.x;
    const int n = tid & 127;
    const uint32_t* src = (tid < 128 ? wh : wl) + n * LDA32 + w * 8;
    uint32_t* dst = reinterpret_cast<uint32_t*>(
        smem + (tid < 128 ? SM_BH : SM_BL)) + n * LDB32;
    uint4 v0 = __ldg(reinterpret_cast<const uint4*>(src));
    uint4 v1 = __ldg(reinterpret_cast<const uint4*>(src + 4));
    dst[0] = v0.x; dst[1] = v0.y; dst[2] = v0.z; dst[3] = v0.w;
    dst[4] = v1.x; dst[5] = v1.y; dst[6] = v1.z; dst[7] = v1.w;
}

__global__ void __launch_bounds__(256, 2)
mlp_mma_kernel(const float* __restrict__ H,
               const uint32_t* __restrict__ wh1, const uint32_t* __restrict__ wl1,
               const uint32_t* __restrict__ wh2, const uint32_t* __restrict__ wl2,
               const float* __restrict__ b1, const float* __restrict__ b2,
               float* __restrict__ out, int M) {
    extern __shared__ char smem[];
    uint32_t* ah32 = reinterpret_cast<uint32_t*>(smem + SM_AH);
    uint32_t* al32 = reinterpret_cast<uint32_t*>(smem + SM_AL);
    uint32_t* bh32 = reinterpret_cast<uint32_t*>(smem + SM_BH);
    uint32_t* bl32 = reinterpret_cast<uint32_t*>(smem + SM_BL);
    float* bias1 = reinterpret_cast<float*>(smem + SM_BIAS1);
    float* bias2 = reinterpret_cast<float*>(smem + SM_BIAS2);

    const int tid = threadIdx.x;
    const int wid = tid >> 5;
    const int lane = tid & 31;
    const int g = lane >> 2;
    const int t = lane & 3;
    const int warp_m = wid & 3;
    const int warp_n = wid >> 2;
    const int row_base = blockIdx.x * 128;

    if (tid < 128) bias1[tid] = __ldg(b1 + tid);
    else           bias2[tid - 128] = __ldg(b2 + tid - 128);

    // ---- load H tile, split into Ah/Al ----
    {
        const int row = tid >> 1;
        const int c0 = (tid & 1) * 64;
        const bool valid = (row_base + row) < M;
        const float4* src = reinterpret_cast<const float4*>(
            H + (size_t)(row_base + row) * D + c0);
        uint32_t* dh = ah32 + row * LDA32 + (c0 >> 1);
        uint32_t* dl = al32 + row * LDA32 + (c0 >> 1);
        #pragma unroll
        for (int q = 0; q < 16; q++) {
            float4 v = valid ? __ldg(src + q) : make_float4(0.f, 0.f, 0.f, 0.f);
            uint32_t h0, l0, h1, l1;
            split_pair(v.x, v.y, h0, l0);
            split_pair(v.z, v.w, h1, l1);
            dh[q * 2]     = h0;  dh[q * 2 + 1] = h1;
            dl[q * 2]     = l0;  dl[q * 2 + 1] = l1;
        }
    }

    float acc[2][8][4];
    #pragma unroll
    for (int i = 0; i < 2; i++)
        #pragma unroll
        for (int j = 0; j < 8; j++)
            #pragma unroll
            for (int c = 0; c < 4; c++) acc[i][j][c] = 0.f;

    // =============== GEMM1 ===============
    #pragma unroll 1
    for (int w = 0; w < 8; w++) {
        __syncthreads();
        copy_w_chunk(wh1, wl1, w, smem);
        __syncthreads();

        const int kw = w * 8;
        uint32_t ah[2][4], al[2][4];
        #pragma unroll
        for (int mt = 0; mt < 2; mt++) {
            const int r0 = warp_m * 32 + mt * 16 + g;
            const uint32_t* ph = ah32 + r0 * LDA32 + kw + t;
            const uint32_t* pl = al32 + r0 * LDA32 + kw + t;
            ah[mt][0] = ph[0];  ah[mt][2] = ph[4];
            ah[mt][1] = ph[8 * LDA32];  ah[mt][3] = ph[8 * LDA32 + 4];
            al[mt][0] = pl[0];  al[mt][2] = pl[4];
            al[mt][1] = pl[8 * LDA32];  al[mt][3] = pl[8 * LDA32 + 4];
        }
        #pragma unroll
        for (int nt = 0; nt < 8; nt++) {
            const int nr = warp_n * 64 + nt * 8 + g;
            uint32_t bh0 = bh32[nr * LDB32 + t];
            uint32_t bh1 = bh32[nr * LDB32 + t + 4];
            uint32_t bl0 = bl32[nr * LDB32 + t];
            uint32_t bl1 = bl32[nr * LDB32 + t + 4];
            #pragma unroll
            for (int mt = 0; mt < 2; mt++) {
                mma_bf16(acc[mt][nt], ah[mt], bh0, bh1);
                mma_bf16(acc[mt][nt], al[mt], bh0, bh1);
                mma_bf16(acc[mt][nt], ah[mt], bl0, bl1);
            }
        }
    }

    // ---- epilogue 1: bias + relu, re-split into Ah/Al ----
    __syncthreads();
    #pragma unroll
    for (int mt = 0; mt < 2; mt++) {
        const int rl = warp_m * 32 + mt * 16 + g;
        #pragma unroll
        for (int nt = 0; nt < 8; nt++) {
            const int cb = warp_n * 64 + nt * 8 + t * 2;
            float v0 = fmaxf(acc[mt][nt][0] + bias1[cb],     0.f);
            float v1 = fmaxf(acc[mt][nt][1] + bias1[cb + 1], 0.f);
            float v2 = fmaxf(acc[mt][nt][2] + bias1[cb],     0.f);
            float v3 = fmaxf(acc[mt][nt][3] + bias1[cb + 1], 0.f);
            uint32_t hi, lo;
            split_pair(v0, v1, hi, lo);
            ah32[rl * LDA32 + (cb >> 1)] = hi;
            al32[rl * LDA32 + (cb >> 1)] = lo;
            split_pair(v2, v3, hi, lo);
            ah32[(rl + 8) * LDA32 + (cb >> 1)] = hi;
            al32[(rl + 8) * LDA32 + (cb >> 1)] = lo;
            acc[mt][nt][0] = 0.f; acc[mt][nt][1] = 0.f;
            acc[mt][nt][2] = 0.f; acc[mt][nt][3] = 0.f;
        }
    }

    // =============== GEMM2 ===============
    #pragma unroll 1
    for (int w = 0; w < 8; w++) {
        __syncthreads();
        copy_w_chunk(wh2, wl2, w, smem);
        __syncthreads();

        const int kw = w * 8;
        uint32_t ah[2][4], al[2][4];
        #pragma unroll
        for (int mt = 0; mt < 2; mt++) {
            const int r0 = warp_m * 32 + mt * 16 + g;
            const uint32_t* ph = ah32 + r0 * LDA32 + kw + t;
            const uint32_t* pl = al32 + r0 * LDA32 + kw + t;
            ah[mt][0] = ph[0];  ah[mt][2] = ph[4];
            ah[mt][1] = ph[8 * LDA32];  ah[mt][3] = ph[8 * LDA32 + 4];
            al[mt][0] = pl[0];  al[mt][2] = pl[4];
            al[mt][1] = pl[8 * LDA32];  al[mt][3] = pl[8 * LDA32 + 4];
        }
        #pragma unroll
        for (int nt = 0; nt < 8; nt++) {
            const int nr = warp_n * 64 + nt * 8 + g;
            uint32_t bh0 = bh32[nr * LDB32 + t];
            uint32_t bh1 = bh32[nr * LDB32 + t + 4];
            uint32_t bl0 = bl32[nr * LDB32 + t];
            uint32_t bl1 = bl32[nr * LDB32 + t + 4];
            #pragma unroll
            for (int mt = 0; mt < 2; mt++) {
                mma_bf16(acc[mt][nt], ah[mt], bh0, bh1);
                mma_bf16(acc[mt][nt], al[mt], bh0, bh1);
                mma_bf16(acc[mt][nt], ah[mt], bl0, bl1);
            }
        }
    }

    // ---- epilogue 2: bias -> out ----
    #pragma unroll
    for (int mt = 0; mt < 2; mt++) {
        const int rl = warp_m * 32 + mt * 16 + g;
        #pragma unroll
        for (int nt = 0; nt < 8; nt++) {
            const int cb = warp_n * 64 + nt * 8 + t * 2;
            if (row_base + rl < M) {
                float2 o;
                o.x = acc[mt][nt][0] + bias2[cb];
                o.y = acc[mt][nt][1] + bias2[cb + 1];
                *reinterpret_cast<float2*>(out + (size_t)(row_base + rl) * D + cb) = o;
            }
            if (row_base + rl + 8 < M) {
                float2 o;
                o.x = acc[mt][nt][2] + bias2[cb];
                o.y = acc[mt][nt][3] + bias2[cb + 1];
                *reinterpret_cast<float2*>(out + (size_t)(row_base + rl + 8) * D + cb) = o;
            }
        }
    }
}

extern "C" void kernel_launch(void* const* d_in, const int* in_sizes, int n_in,
                              void* d_out, int out_size) {
    const float* x  = (const float*)d_in[0];
    const void*  ei = d_in[1];
    const float* W1 = (const float*)d_in[2];
    const float* b1 = (const float*)d_in[3];
    const float* W2 = (const float*)d_in[4];
    const float* b2 = (const float*)d_in[5];
    float* out = (float*)d_out;

    const int N = in_sizes[0] / D;
    const int E = in_sizes[1] / 2;

    float* p_h    = nullptr;
    int*   p_deg  = nullptr;
    int*   p_csrc = nullptr;
    uint32_t *p_wh1 = nullptr, *p_wl1 = nullptr, *p_wh2 = nullptr, *p_wl2 = nullptr;
    cudaGetSymbolAddress((void**)(&p_h),    g_h);
    cudaGetSymbolAddress((void**)(&p_deg),  g_degcnt);
    cudaGetSymbolAddress((void**)(&p_csrc), g_csrc);
    cudaGetSymbolAddress((void**)(&p_wh1),  g_wh1);
    cudaGetSymbolAddress((void**)(&p_wl1),  g_wl1);
    cudaGetSymbolAddress((void**)(&p_wh2),  g_wh2);
    cudaGetSymbolAddress((void**)(&p_wl2),  g_wl2);

    static int attr_set = 0;
    if (!attr_set) {
        cudaFuncSetAttribute(mlp_mma_kernel,
                             cudaFuncAttributeMaxDynamicSharedMemorySize,
                             SM_MLP_TOTAL);
        attr_set = 1;
    }

    detect_kernel<<<1, 32>>>((const int*)ei);
    wsplit_kernel<<<dim3(128, 2), 128>>>(W1, W2);

    zero_deg_kernel<<<(N / 4 + 255) / 256, 256>>>(p_deg, N);
    build_kernel<<<(E / 4 + 255) / 256, 256>>>(ei, E, p_deg, p_csrc);

    agg_kernel<<<(N + 7) / 8, 256>>>(x, p_csrc, p_deg, p_h, N);

    int ntiles = (N + 127) / 128;
    mlp_mma_kernel<<<ntiles, 256, SM_MLP_TOTAL>>>(p_h, p_wh1, p_wl1,
                                                  p_wh2, p_wl2,
                                                  b1, b2, out, N);
}

// round 16
// speedup vs baseline: 1.1002x; 1.0729x over previous
#include <cuda_runtime.h>
#include <cuda_bf16.h>
#include <cstdint>

#define N_NODES 50000
#define N_EDGES_MAX 1600000
#define D 128
#define EPS 0.001f
#define CAP 128                  // per-node bucket capacity (P(overflow)~1e-13)

// Scratch (allocation-free rule: __device__ globals)
__device__ float g_h[(size_t)N_NODES * D];
__device__ int   g_degcnt[N_NODES];
__device__ int   g_csrc[(size_t)N_NODES * CAP];   // padded CSR: src ids
__device__ int   g_is64;
// Preconverted weight splits, [n][k] bf16, row stride 136
__device__ __nv_bfloat16 g_wh1[128 * 136];
__device__ __nv_bfloat16 g_wl1[128 * 136];
__device__ __nv_bfloat16 g_wh2[128 * 136];
__device__ __nv_bfloat16 g_wl2[128 * 136];

// ===========================================================================
// Fused prologue: edge-width detect + weight split + degree zeroing.
// Blocks 0..127: wsplit (block b = K row b; tid<128 -> W1, else W2).
// Blocks 128..176: zero degcnt (int4).
// Block 0, thread 0 additionally runs detection.
// ===========================================================================
__global__ void prep_kernel(const int* __restrict__ e32,
                            const float* __restrict__ W1,
                            const float* __restrict__ W2,
                            int* __restrict__ degcnt, int N) {
    const int bid = blockIdx.x;
    const int tid = threadIdx.x;
    if (bid == 0 && tid == 0) {
        int is64 = 1;
        #pragma unroll 1
        for (int k = 1; k < 128; k += 2) {
            if (e32[k] != 0) { is64 = 0; break; }
        }
        g_is64 = is64;
    }
    if (bid < 128) {
        const int k = bid;
        const int n = tid & 127;
        const bool second = tid >= 128;
        const float* W = second ? W2 : W1;
        __nv_bfloat16* wh = second ? g_wh2 : g_wh1;
        __nv_bfloat16* wl = second ? g_wl2 : g_wl1;
        float v = __ldg(W + (size_t)k * D + n);
        __nv_bfloat16 h = __float2bfloat16(v);
        __nv_bfloat16 l = __float2bfloat16(v - __bfloat162float(h));
        wh[n * 136 + k] = h;
        wl[n * 136 + k] = l;
    } else {
        int i = (bid - 128) * 256 + tid;          // int4 index
        if (i * 4 < N) {
            if (i * 4 + 3 < N)
                *reinterpret_cast<int4*>(degcnt + i * 4) = make_int4(0, 0, 0, 0);
            else
                for (int k = i * 4; k < N; k++) degcnt[k] = 0;
        }
    }
}

// ===========================================================================
// Padded-CSR build (R13 version: 4 edges/thread — measured best).
// ===========================================================================
__global__ void build_kernel(const void* __restrict__ ei, int E,
                             int* __restrict__ degcnt, int* __restrict__ csrc) {
    int i4 = (blockIdx.x * blockDim.x + threadIdx.x) * 4;
    if (i4 >= E) return;
    int ss[4], dd[4];
    int cnt = (E - i4 < 4) ? (E - i4) : 4;
    if (g_is64) {
        const longlong2* eb = reinterpret_cast<const longlong2*>(ei);
        if (cnt == 4) {
            longlong2 s0 = __ldg(eb + (i4 >> 1));
            longlong2 s1 = __ldg(eb + (i4 >> 1) + 1);
            longlong2 d0 = __ldg(eb + (size_t)(E >> 1) + (i4 >> 1));
            longlong2 d1 = __ldg(eb + (size_t)(E >> 1) + (i4 >> 1) + 1);
            ss[0] = (int)s0.x; ss[1] = (int)s0.y; ss[2] = (int)s1.x; ss[3] = (int)s1.y;
            dd[0] = (int)d0.x; dd[1] = (int)d0.y; dd[2] = (int)d1.x; dd[3] = (int)d1.y;
        } else {
            const long long* e = reinterpret_cast<const long long*>(ei);
            for (int k = 0; k < cnt; k++) {
                ss[k] = (int)__ldg(e + i4 + k);
                dd[k] = (int)__ldg(e + (size_t)E + i4 + k);
            }
        }
    } else {
        const int* e = reinterpret_cast<const int*>(ei);
        if (cnt == 4) {
            int4 s = __ldg(reinterpret_cast<const int4*>(e + i4));
            int4 d = __ldg(reinterpret_cast<const int4*>(e + (size_t)E + i4));
            ss[0] = s.x; ss[1] = s.y; ss[2] = s.z; ss[3] = s.w;
            dd[0] = d.x; dd[1] = d.y; dd[2] = d.z; dd[3] = d.w;
        } else {
            for (int k = 0; k < cnt; k++) {
                ss[k] = __ldg(e + i4 + k);
                dd[k] = __ldg(e + (size_t)E + i4 + k);
            }
        }
    }
    #pragma unroll
    for (int k = 0; k < 4; k++) {
        if (k < cnt) {
            int rank = atomicAdd(degcnt + dd[k], 1);
            if (rank < CAP)
                csrc[(size_t)dd[k] * CAP + rank] = ss[k];
        }
    }
}

// ===========================================================================
// Aggregation: one warp per node (byte-identical to R13 pass).
// ===========================================================================
__global__ void agg_kernel(const float* __restrict__ x,
                           const int* __restrict__ csrc,
                           const int* __restrict__ degcnt,
                           float* __restrict__ h, int N) {
    int w = (blockIdx.x * blockDim.x + threadIdx.x) >> 5;
    int lane = threadIdx.x & 31;
    if (w >= N) return;

    float4 acc = *reinterpret_cast<const float4*>(x + (size_t)w * D + lane * 4);
    const float sc = 1.0f + EPS;
    acc.x *= sc; acc.y *= sc; acc.z *= sc; acc.w *= sc;

    const int* lst = csrc + (size_t)w * CAP;
    int deg = degcnt[w];
    if (deg > CAP) deg = CAP;
    int j = 0;
    for (; j + 4 <= deg; j += 4) {
        int a0 = __ldg(lst + j),     a1 = __ldg(lst + j + 1);
        int a2 = __ldg(lst + j + 2), a3 = __ldg(lst + j + 3);
        float4 v0 = *reinterpret_cast<const float4*>(x + (size_t)a0 * D + lane * 4);
        float4 v1 = *reinterpret_cast<const float4*>(x + (size_t)a1 * D + lane * 4);
        float4 v2 = *reinterpret_cast<const float4*>(x + (size_t)a2 * D + lane * 4);
        float4 v3 = *reinterpret_cast<const float4*>(x + (size_t)a3 * D + lane * 4);
        acc.x += (v0.x + v1.x) + (v2.x + v3.x);
        acc.y += (v0.y + v1.y) + (v2.y + v3.y);
        acc.z += (v0.z + v1.z) + (v2.z + v3.z);
        acc.w += (v0.w + v1.w) + (v2.w + v3.w);
    }
    for (; j < deg; j++) {
        int a0 = __ldg(lst + j);
        float4 v0 = *reinterpret_cast<const float4*>(x + (size_t)a0 * D + lane * 4);
        acc.x += v0.x; acc.y += v0.y; acc.z += v0.z; acc.w += v0.w;
    }
    *reinterpret_cast<float4*>(h + (size_t)w * D + lane * 4) = acc;
}

// ===========================================================================
// Tensor-core MLP — mma.sync bf16 3-pass split, 2 CTA/SM.
// 32-column W chunks (4 loop iterations per GEMM instead of 8; barriers
// halved; SMEM 89KB keeps occupancy 2 and register budget unchanged).
// ===========================================================================
#define LDA32 68                 // uint32 stride of Ah/Al rows (136 bf16)
#define LDB32 18                 // uint32 stride of B chunk rows (36 bf16)
#define SM_BIAS1 0
#define SM_BIAS2 512
#define SM_AH    1024
#define SM_AL    (SM_AH + 128 * LDA32 * 4)
#define SM_BH    (SM_AL + 128 * LDA32 * 4)
#define SM_BL    (SM_BH + 128 * LDB32 * 4)
#define SM_MLP_TOTAL (SM_BL + 128 * LDB32 * 4)      // 89088 bytes

__device__ __forceinline__ void split_pair(float v0, float v1,
                                           uint32_t& hi, uint32_t& lo) {
    __nv_bfloat16 h0 = __float2bfloat16(v0);
    __nv_bfloat16 h1 = __float2bfloat16(v1);
    __nv_bfloat16 l0 = __float2bfloat16(v0 - __bfloat162float(h0));
    __nv_bfloat16 l1 = __float2bfloat16(v1 - __bfloat162float(h1));
    __nv_bfloat162 ph; ph.x = h0; ph.y = h1;
    __nv_bfloat162 pl; pl.x = l0; pl.y = l1;
    hi = *reinterpret_cast<uint32_t*>(&ph);
    lo = *reinterpret_cast<uint32_t*>(&pl);
}

__device__ __forceinline__ void mma_bf16(float* c,
                                         const uint32_t* a,
                                         uint32_t b0, uint32_t b1) {
    asm volatile(
        "mma.sync.aligned.m16n8k16.row.col.f32.bf16.bf16.f32 "
        "{%0,%1,%2,%3}, {%4,%5,%6,%7}, {%8,%9}, {%0,%1,%2,%3};"
        : "+f"(c[0]), "+f"(c[1]), "+f"(c[2]), "+f"(c[3])
        : "r"(a[0]), "r"(a[1]), "r"(a[2]), "r"(a[3]), "r"(b0), "r"(b1));
}

// Copy one 32-col k-chunk (uint cols w*16..w*16+15) into SMEM chunk buffers.
// tid<128: hi rows; tid>=128: lo rows. 16 uints per thread, 4x uint4.
__device__ __forceinline__ void copy_w_chunk(const uint32_t* __restrict__ wh,
                                             const uint32_t* __restrict__ wl,
                                             int w, char* smem) {
    const int tid = threadIdx.x;
    const int n = tid & 127;
    const uint32_t* src = (tid < 128 ? wh : wl) + n * LDA32 + w * 16;
    uint32_t* dst = reinterpret_cast<uint32_t*>(
        smem + (tid < 128 ? SM_BH : SM_BL)) + n * LDB32;
    #pragma unroll
    for (int q = 0; q < 4; q++) {
        uint4 v = __ldg(reinterpret_cast<const uint4*>(src + q * 4));
        dst[q * 4 + 0] = v.x; dst[q * 4 + 1] = v.y;
        dst[q * 4 + 2] = v.z; dst[q * 4 + 3] = v.w;
    }
}

__global__ void __launch_bounds__(256, 2)
mlp_mma_kernel(const float* __restrict__ H,
               const uint32_t* __restrict__ wh1, const uint32_t* __restrict__ wl1,
               const uint32_t* __restrict__ wh2, const uint32_t* __restrict__ wl2,
               const float* __restrict__ b1, const float* __restrict__ b2,
               float* __restrict__ out, int M) {
    extern __shared__ char smem[];
    uint32_t* ah32 = reinterpret_cast<uint32_t*>(smem + SM_AH);
    uint32_t* al32 = reinterpret_cast<uint32_t*>(smem + SM_AL);
    uint32_t* bh32 = reinterpret_cast<uint32_t*>(smem + SM_BH);
    uint32_t* bl32 = reinterpret_cast<uint32_t*>(smem + SM_BL);
    float* bias1 = reinterpret_cast<float*>(smem + SM_BIAS1);
    float* bias2 = reinterpret_cast<float*>(smem + SM_BIAS2);

    const int tid = threadIdx.x;
    const int wid = tid >> 5;
    const int lane = tid & 31;
    const int g = lane >> 2;
    const int t = lane & 3;
    const int warp_m = wid & 3;
    const int warp_n = wid >> 2;
    const int row_base = blockIdx.x * 128;

    if (tid < 128) bias1[tid] = __ldg(b1 + tid);
    else           bias2[tid - 128] = __ldg(b2 + tid - 128);

    // ---- load H tile, split into Ah/Al ----
    {
        const int row = tid >> 1;
        const int c0 = (tid & 1) * 64;
        const bool valid = (row_base + row) < M;
        const float4* src = reinterpret_cast<const float4*>(
            H + (size_t)(row_base + row) * D + c0);
        uint32_t* dh = ah32 + row * LDA32 + (c0 >> 1);
        uint32_t* dl = al32 + row * LDA32 + (c0 >> 1);
        #pragma unroll
        for (int q = 0; q < 16; q++) {
            float4 v = valid ? __ldg(src + q) : make_float4(0.f, 0.f, 0.f, 0.f);
            uint32_t h0, l0, h1, l1;
            split_pair(v.x, v.y, h0, l0);
            split_pair(v.z, v.w, h1, l1);
            dh[q * 2]     = h0;  dh[q * 2 + 1] = h1;
            dl[q * 2]     = l0;  dl[q * 2 + 1] = l1;
        }
    }

    float acc[2][8][4];
    #pragma unroll
    for (int i = 0; i < 2; i++)
        #pragma unroll
        for (int j = 0; j < 8; j++)
            #pragma unroll
            for (int c = 0; c < 4; c++) acc[i][j][c] = 0.f;

    // =============== GEMM1 (4 chunks of 32 cols) ===============
    #pragma unroll 1
    for (int w = 0; w < 4; w++) {
        __syncthreads();
        copy_w_chunk(wh1, wl1, w, smem);
        __syncthreads();

        #pragma unroll
        for (int kw2 = 0; kw2 < 2; kw2++) {
            const int kwu = w * 16 + kw2 * 8;       // uint col base into A
            const int kb  = kw2 * 8;                // uint col base into chunk
            uint32_t ah[2][4], al[2][4];
            #pragma unroll
            for (int mt = 0; mt < 2; mt++) {
                const int r0 = warp_m * 32 + mt * 16 + g;
                const uint32_t* ph = ah32 + r0 * LDA32 + kwu + t;
                const uint32_t* pl = al32 + r0 * LDA32 + kwu + t;
                ah[mt][0] = ph[0];  ah[mt][2] = ph[4];
                ah[mt][1] = ph[8 * LDA32];  ah[mt][3] = ph[8 * LDA32 + 4];
                al[mt][0] = pl[0];  al[mt][2] = pl[4];
                al[mt][1] = pl[8 * LDA32];  al[mt][3] = pl[8 * LDA32 + 4];
            }
            #pragma unroll
            for (int nt = 0; nt < 8; nt++) {
                const int nr = warp_n * 64 + nt * 8 + g;
                uint32_t bh0 = bh32[nr * LDB32 + kb + t];
                uint32_t bh1 = bh32[nr * LDB32 + kb + t + 4];
                uint32_t bl0 = bl32[nr * LDB32 + kb + t];
                uint32_t bl1 = bl32[nr * LDB32 + kb + t + 4];
                #pragma unroll
                for (int mt = 0; mt < 2; mt++) {
                    mma_bf16(acc[mt][nt], ah[mt], bh0, bh1);
                    mma_bf16(acc[mt][nt], al[mt], bh0, bh1);
                    mma_bf16(acc[mt][nt], ah[mt], bl0, bl1);
                }
            }
        }
    }

    // ---- epilogue 1: bias + relu, re-split into Ah/Al ----
    __syncthreads();
    #pragma unroll
    for (int mt = 0; mt < 2; mt++) {
        const int rl = warp_m * 32 + mt * 16 + g;
        #pragma unroll
        for (int nt = 0; nt < 8; nt++) {
            const int cb = warp_n * 64 + nt * 8 + t * 2;
            float v0 = fmaxf(acc[mt][nt][0] + bias1[cb],     0.f);
            float v1 = fmaxf(acc[mt][nt][1] + bias1[cb + 1], 0.f);
            float v2 = fmaxf(acc[mt][nt][2] + bias1[cb],     0.f);
            float v3 = fmaxf(acc[mt][nt][3] + bias1[cb + 1], 0.f);
            uint32_t hi, lo;
            split_pair(v0, v1, hi, lo);
            ah32[rl * LDA32 + (cb >> 1)] = hi;
            al32[rl * LDA32 + (cb >> 1)] = lo;
            split_pair(v2, v3, hi, lo);
            ah32[(rl + 8) * LDA32 + (cb >> 1)] = hi;
            al32[(rl + 8) * LDA32 + (cb >> 1)] = lo;
            acc[mt][nt][0] = 0.f; acc[mt][nt][1] = 0.f;
            acc[mt][nt][2] = 0.f; acc[mt][nt][3] = 0.f;
        }
    }

    // =============== GEMM2 (4 chunks of 32 cols) ===============
    #pragma unroll 1
    for (int w = 0; w < 4; w++) {
        __syncthreads();
        copy_w_chunk(wh2, wl2, w, smem);
        __syncthreads();

        #pragma unroll
        for (int kw2 = 0; kw2 < 2; kw2++) {
            const int kwu = w * 16 + kw2 * 8;
            const int kb  = kw2 * 8;
            uint32_t ah[2][4], al[2][4];
            #pragma unroll
            for (int mt = 0; mt < 2; mt++) {
                const int r0 = warp_m * 32 + mt * 16 + g;
                const uint32_t* ph = ah32 + r0 * LDA32 + kwu + t;
                const uint32_t* pl = al32 + r0 * LDA32 + kwu + t;
                ah[mt][0] = ph[0];  ah[mt][2] = ph[4];
                ah[mt][1] = ph[8 * LDA32];  ah[mt][3] = ph[8 * LDA32 + 4];
                al[mt][0] = pl[0];  al[mt][2] = pl[4];
                al[mt][1] = pl[8 * LDA32];  al[mt][3] = pl[8 * LDA32 + 4];
            }
            #pragma unroll
            for (int nt = 0; nt < 8; nt++) {
                const int nr = warp_n * 64 + nt * 8 + g;
                uint32_t bh0 = bh32[nr * LDB32 + kb + t];
                uint32_t bh1 = bh32[nr * LDB32 + kb + t + 4];
                uint32_t bl0 = bl32[nr * LDB32 + kb + t];
                uint32_t bl1 = bl32[nr * LDB32 + kb + t + 4];
                #pragma unroll
                for (int mt = 0; mt < 2; mt++) {
                    mma_bf16(acc[mt][nt], ah[mt], bh0, bh1);
                    mma_bf16(acc[mt][nt], al[mt], bh0, bh1);
                    mma_bf16(acc[mt][nt], ah[mt], bl0, bl1);
                }
            }
        }
    }

    // ---- epilogue 2: bias -> out ----
    #pragma unroll
    for (int mt = 0; mt < 2; mt++) {
        const int rl = warp_m * 32 + mt * 16 + g;
        #pragma unroll
        for (int nt = 0; nt < 8; nt++) {
            const int cb = warp_n * 64 + nt * 8 + t * 2;
            if (row_base + rl < M) {
                float2 o;
                o.x = acc[mt][nt][0] + bias2[cb];
                o.y = acc[mt][nt][1] + bias2[cb + 1];
                *reinterpret_cast<float2*>(out + (size_t)(row_base + rl) * D + cb) = o;
            }
            if (row_base + rl + 8 < M) {
                float2 o;
                o.x = acc[mt][nt][2] + bias2[cb];
                o.y = acc[mt][nt][3] + bias2[cb + 1];
                *reinterpret_cast<float2*>(out + (size_t)(row_base + rl + 8) * D + cb) = o;
            }
        }
    }
}

extern "C" void kernel_launch(void* const* d_in, const int* in_sizes, int n_in,
                              void* d_out, int out_size) {
    const float* x  = (const float*)d_in[0];
    const void*  ei = d_in[1];
    const float* W1 = (const float*)d_in[2];
    const float* b1 = (const float*)d_in[3];
    const float* W2 = (const float*)d_in[4];
    const float* b2 = (const float*)d_in[5];
    float* out = (float*)d_out;

    const int N = in_sizes[0] / D;
    const int E = in_sizes[1] / 2;

    float* p_h    = nullptr;
    int*   p_deg  = nullptr;
    int*   p_csrc = nullptr;
    uint32_t *p_wh1 = nullptr, *p_wl1 = nullptr, *p_wh2 = nullptr, *p_wl2 = nullptr;
    cudaGetSymbolAddress((void**)(&p_h),    g_h);
    cudaGetSymbolAddress((void**)(&p_deg),  g_degcnt);
    cudaGetSymbolAddress((void**)(&p_csrc), g_csrc);
    cudaGetSymbolAddress((void**)(&p_wh1),  g_wh1);
    cudaGetSymbolAddress((void**)(&p_wl1),  g_wl1);
    cudaGetSymbolAddress((void**)(&p_wh2),  g_wh2);
    cudaGetSymbolAddress((void**)(&p_wl2),  g_wl2);

    static int attr_set = 0;
    if (!attr_set) {
        cudaFuncSetAttribute(mlp_mma_kernel,
                             cudaFuncAttributeMaxDynamicSharedMemorySize,
                             SM_MLP_TOTAL);
        attr_set = 1;
    }

    // fused prologue: detect + wsplit + zero (one launch)
    const int zero_blocks = ((N + 3) / 4 + 255) / 256;   // 49
    prep_kernel<<<128 + zero_blocks, 256>>>((const int*)ei, W1, W2, p_deg, N);

    build_kernel<<<(E / 4 + 255) / 256, 256>>>(ei, E, p_deg, p_csrc);

    agg_kernel<<<(N + 7) / 8, 256>>>(x, p_csrc, p_deg, p_h, N);

    int ntiles = (N + 127) / 128;
    mlp_mma_kernel<<<ntiles, 256, SM_MLP_TOTAL>>>(p_h, p_wh1, p_wl1,
                                                  p_wh2, p_wl2,
                                                  b1, b2, out, N);
}